// round 1
// baseline (speedup 1.0000x reference)
#include <cuda_runtime.h>
#include <cstdint>

// ============================================================================
// DynamicConv1D: T=2048, B=16, C=512, H=8, R=64, K=7
//   phase 1: logits = query @ W  (32768 x 512) * (512 x 56), softmax over K=7
//            per (row, head); store to scratch padded to 8 floats per (row,head)
//   phase 2: out[t,b,h*64+r] = sum_kk w[t,b,h,kk] * xwin[t, f],  f = h*448+r*7+kk
//            where xwin is the 7x512 padded window starting at t-3.
//            Since window rows have width exactly C=512, the 7 taps are
//            CONSECUTIVE addresses in a [38 x 512] smem tile: xs[tl*512 + f + kk].
// ============================================================================

#define T_DIM 2048
#define B_DIM 16
#define C_DIM 512
#define H_DIM 8
#define K_DIM 7

// scratch: softmaxed weights, padded: [(t*B+b) * 8 heads * 8 slots]
__device__ float g_weights[(size_t)T_DIM * B_DIM * H_DIM * 8];

// ---------------------------------------------------------------------------
// Kernel 1: GEMM (M=32768, N=56, K=512) + fused softmax.
// BM=128 rows/block, BK=32, 256 threads. Thread = (rowGroup = tid>>3 -> 4 rows,
// head = tid&7 -> 7 cols). FFMA2 via fma.rn.f32x2: acc rows packed in pairs.
// ---------------------------------------------------------------------------
#define BM 128
#define BK 32

__device__ __forceinline__ unsigned long long fma2(unsigned long long a,
                                                   unsigned long long b,
                                                   unsigned long long c) {
    asm("fma.rn.f32x2 %0, %1, %2, %0;" : "+l"(c) : "l"(a), "l"(b));
    return c;
}

__global__ __launch_bounds__(256, 2)
void gemm_softmax_kernel(const float* __restrict__ query,
                         const float* __restrict__ W) {
    __shared__ float  As[BK][BM];      // K-major A tile: 16 KB
    __shared__ float2 Bs[BK][80];      // duplicated W: slot = head*10 + jj, 20 KB
                                       // stride 10 float2 = 80B -> head*20 mod 32 banks all distinct

    const int tid      = threadIdx.x;
    const int head     = tid & 7;
    const int rbase    = (tid >> 3) * 4;          // 0..124
    const int blockRow = blockIdx.x * BM;

    unsigned long long accP[2][7];
    #pragma unroll
    for (int p = 0; p < 2; p++)
        #pragma unroll
        for (int j = 0; j < 7; j++) accP[p][j] = 0ULL;

    for (int k0 = 0; k0 < C_DIM; k0 += BK) {
        // ---- load A tile (128 x 32), store K-major ----
        #pragma unroll
        for (int l = 0; l < 4; l++) {
            int linear = tid + l * 256;       // 0..1023
            int row    = linear >> 3;         // 0..127
            int f4     = linear & 7;          // 0..7
            float4 v = *(const float4*)(query + (size_t)(blockRow + row) * C_DIM + k0 + f4 * 4);
            As[f4 * 4 + 0][row] = v.x;
            As[f4 * 4 + 1][row] = v.y;
            As[f4 * 4 + 2][row] = v.z;
            As[f4 * 4 + 3][row] = v.w;
        }
        // ---- load B tile, lane-duplicated float2, head-padded ----
        #pragma unroll
        for (int l = 0; l < 10; l++) {
            int linear = tid + l * 256;       // 0..2559
            int kk   = linear / 80;
            int slot = linear - kk * 80;
            int hs   = slot / 10;
            int jj   = slot - hs * 10;
            float w = 0.0f;
            if (jj < 7) w = W[(k0 + kk) * 56 + hs * 7 + jj];
            Bs[kk][slot] = make_float2(w, w);
        }
        __syncthreads();

        #pragma unroll
        for (int kk = 0; kk < BK; kk++) {
            // A fragment: 4 consecutive rows -> 2 natural f32x2 packs
            ulonglong2 a = *(const ulonglong2*)&As[kk][rbase];
            const ulonglong2* bp = (const ulonglong2*)&Bs[kk][head * 10];
            ulonglong2 b01 = bp[0], b23 = bp[1], b45 = bp[2], b67 = bp[3];
            unsigned long long b[7] = {b01.x, b01.y, b23.x, b23.y, b45.x, b45.y, b67.x};
            #pragma unroll
            for (int j = 0; j < 7; j++) {
                accP[0][j] = fma2(a.x, b[j], accP[0][j]);
                accP[1][j] = fma2(a.y, b[j], accP[1][j]);
            }
        }
        __syncthreads();
    }

    // ---- unpack, softmax over the 7 taps, store padded to 8 ----
    #pragma unroll
    for (int p = 0; p < 2; p++) {
        float lo[7], hi[7];
        #pragma unroll
        for (int j = 0; j < 7; j++) {
            unsigned int ulo, uhi;
            asm("mov.b64 {%0, %1}, %2;" : "=r"(ulo), "=r"(uhi) : "l"(accP[p][j]));
            lo[j] = __uint_as_float(ulo);
            hi[j] = __uint_as_float(uhi);
        }
        #pragma unroll
        for (int half = 0; half < 2; half++) {
            float* v = half ? hi : lo;
            int rowGlobal = blockRow + rbase + 2 * p + half;
            float m = v[0];
            #pragma unroll
            for (int j = 1; j < 7; j++) m = fmaxf(m, v[j]);
            float e[7], s = 0.0f;
            #pragma unroll
            for (int j = 0; j < 7; j++) { e[j] = __expf(v[j] - m); s += e[j]; }
            float inv = 1.0f / s;
            size_t n8 = ((size_t)rowGlobal * 8 + head) * 8;
            *(float4*)&g_weights[n8]     = make_float4(e[0]*inv, e[1]*inv, e[2]*inv, e[3]*inv);
            *(float4*)&g_weights[n8 + 4] = make_float4(e[4]*inv, e[5]*inv, e[6]*inv, 0.0f);
        }
    }
}

// ---------------------------------------------------------------------------
// Kernel 2: gathered conv. Block = (t-tile of 32, one b). 512 threads, thread
// owns one channel c for all 32 t. x staged in smem [38 x 512] (halo 3+3),
// weights staged [32 x 64]. Taps are 7 consecutive smem floats at tl*512 + f.
// ---------------------------------------------------------------------------
#define TT 32
#define XS_ROWS (TT + K_DIM - 1)            // 38
#define SMEM_CONV ((XS_ROWS * C_DIM + TT * 64) * 4)   // 86016 bytes

__global__ __launch_bounds__(512, 2)
void conv_kernel(const float* __restrict__ x, float* __restrict__ out) {
    extern __shared__ float smem[];
    float* xs = smem;                        // 38*512
    float* ws = smem + XS_ROWS * C_DIM;      // 32*64

    const int tid = threadIdx.x;
    const int t0  = (blockIdx.x >> 4) * TT;
    const int b   = blockIdx.x & 15;

    // ---- stage weights: per t, 64 contiguous floats (8 heads x 8 slots) ----
    {
        int tl = tid >> 4;                   // 0..31
        int f4 = tid & 15;                   // 0..15
        const float4* src = (const float4*)(g_weights + (size_t)(t0 + tl) * (B_DIM * 64) + b * 64);
        *(float4*)&ws[tl * 64 + f4 * 4] = src[f4];
    }
    // ---- stage x tile with halo, zero-padded at sequence edges ----
    for (int linear = tid; linear < XS_ROWS * (C_DIM / 4); linear += 512) {
        int irow = linear >> 7;              // 0..37
        int c4   = linear & 127;
        int tg   = t0 - 3 + irow;
        float4 v = make_float4(0.0f, 0.0f, 0.0f, 0.0f);
        if (tg >= 0 && tg < T_DIM)
            v = *(const float4*)(x + ((size_t)tg * B_DIM + b) * C_DIM + c4 * 4);
        *(float4*)&xs[irow * C_DIM + c4 * 4] = v;
    }
    __syncthreads();

    const int c  = tid;
    const int h  = c >> 6;                   // uniform per warp
    const int fb = h * 448 + (c & 63) * 7;   // flat offset of first tap

    #pragma unroll 4
    for (int tl = 0; tl < TT; tl++) {
        const float4* wp = (const float4*)&ws[tl * 64 + h * 8];
        float4 w0 = wp[0];
        float4 w1 = wp[1];
        const float* xp = &xs[tl * C_DIM + fb];   // 7 consecutive floats, lane stride 7 -> conflict-free
        float acc;
        acc = w0.x * xp[0];
        acc = fmaf(w0.y, xp[1], acc);
        acc = fmaf(w0.z, xp[2], acc);
        acc = fmaf(w0.w, xp[3], acc);
        acc = fmaf(w1.x, xp[4], acc);
        acc = fmaf(w1.y, xp[5], acc);
        acc = fmaf(w1.z, xp[6], acc);
        out[((size_t)(t0 + tl) * B_DIM + b) * C_DIM + c] = acc;
    }
}

// ---------------------------------------------------------------------------
extern "C" void kernel_launch(void* const* d_in, const int* in_sizes, int n_in,
                              void* d_out, int out_size) {
    const float* x     = (const float*)d_in[0];
    const float* query = (const float*)d_in[1];
    const float* W     = (const float*)d_in[2];
    float* out         = (float*)d_out;

    cudaFuncSetAttribute(conv_kernel, cudaFuncAttributeMaxDynamicSharedMemorySize, SMEM_CONV);

    // phase 1: 32768 rows / 128 = 256 blocks
    gemm_softmax_kernel<<<256, 256>>>(query, W);
    // phase 2: 64 t-tiles x 16 batches
    conv_kernel<<<(T_DIM / TT) * B_DIM, 512, SMEM_CONV>>>(x, out);
}

// round 2
// speedup vs baseline: 1.8324x; 1.8324x over previous
#include <cuda_runtime.h>
#include <cstdint>

// ============================================================================
// DynamicConv1D: T=2048, B=16, C=512, H=8, R=64, K=7
//   phase 1: logits = query @ W  (32768 x 512) * (512 x 56), softmax over K=7
//            per (row, head); store to scratch padded to 8 floats per (row,head)
//   phase 2: out[t,b,h*64+r] = sum_kk w[t,b,h,kk] * xwin[t, f],  f = h*448+r*7+kk
//            taps are 7 CONSECUTIVE floats in a [rows x 512] smem tile.
// ============================================================================

#define T_DIM 2048
#define B_DIM 16
#define C_DIM 512
#define H_DIM 8
#define K_DIM 7

// scratch: softmaxed weights, padded: [(t*B+b) * 8 heads * 8 slots]
__device__ float g_weights[(size_t)T_DIM * B_DIM * H_DIM * 8];

// ---------------------------------------------------------------------------
// Kernel 1: GEMM (M=32768, N=56, K=512) + fused softmax.
// BM=128 rows/block, BK=32, 256 threads = 8 warps. Warp w <-> head w (B loads
// are warp-uniform BROADCASTS). Thread = 4 rows x 7 cols, rows packed in pairs
// for fma.rn.f32x2 (FFMA2: 2 MACs/lane/instr).
// ---------------------------------------------------------------------------
#define BM 128
#define BK 32

__device__ __forceinline__ unsigned long long fma2(unsigned long long a,
                                                   unsigned long long b,
                                                   unsigned long long c) {
    asm("fma.rn.f32x2 %0, %1, %2, %0;" : "+l"(c) : "l"(a), "l"(b));
    return c;
}

__global__ __launch_bounds__(256, 2)
void gemm_softmax_kernel(const float* __restrict__ query,
                         const float* __restrict__ W) {
    __shared__ float  As[BK][BM];      // K-major A tile: 16 KB
    __shared__ float2 Bsd[BK][64];     // duplicated W: [kk][head*8 + j], 16 KB
                                       // read path is warp-uniform -> broadcast

    const int tid      = threadIdx.x;
    const int lane     = tid & 31;
    const int head     = tid >> 5;                // warp id == head
    const int rbase    = lane * 4;                // 0..124
    const int blockRow = blockIdx.x * BM;

    unsigned long long accP[2][7];
    #pragma unroll
    for (int p = 0; p < 2; p++)
        #pragma unroll
        for (int j = 0; j < 7; j++) accP[p][j] = 0ULL;

    for (int k0 = 0; k0 < C_DIM; k0 += BK) {
        // ---- load A tile (128 x 32), store K-major ----
        #pragma unroll
        for (int l = 0; l < 4; l++) {
            int linear = tid + l * 256;       // 0..1023
            int row    = linear >> 3;         // 0..127
            int f4     = linear & 7;          // 0..7
            float4 v = *(const float4*)(query + (size_t)(blockRow + row) * C_DIM + k0 + f4 * 4);
            As[f4 * 4 + 0][row] = v.x;
            As[f4 * 4 + 1][row] = v.y;
            As[f4 * 4 + 2][row] = v.z;
            As[f4 * 4 + 3][row] = v.w;
        }
        // ---- load B tile, lane-duplicated float2: 2048 elems, 8/thread ----
        #pragma unroll
        for (int l = 0; l < 8; l++) {
            int linear = tid + l * 256;       // 0..2047
            int kk   = linear >> 6;           // 0..31
            int slot = linear & 63;
            int hs   = slot >> 3;
            int jj   = slot & 7;
            float w = 0.0f;
            if (jj < 7) w = W[(k0 + kk) * 56 + hs * 7 + jj];
            Bsd[kk][slot] = make_float2(w, w);
        }
        __syncthreads();

        #pragma unroll
        for (int kk = 0; kk < BK; kk++) {
            // A fragment: 4 consecutive rows -> LDS.128, 2 natural f32x2 packs
            ulonglong2 a = *(const ulonglong2*)&As[kk][rbase];
            // B fragment: warp-uniform -> 4 broadcast LDS.128
            const ulonglong2* bp = (const ulonglong2*)&Bsd[kk][head * 8];
            ulonglong2 b01 = bp[0], b23 = bp[1], b45 = bp[2], b67 = bp[3];
            unsigned long long b[7] = {b01.x, b01.y, b23.x, b23.y, b45.x, b45.y, b67.x};
            #pragma unroll
            for (int j = 0; j < 7; j++) {
                accP[0][j] = fma2(a.x, b[j], accP[0][j]);
                accP[1][j] = fma2(a.y, b[j], accP[1][j]);
            }
        }
        __syncthreads();
    }

    // ---- unpack, softmax over the 7 taps, store padded to 8 ----
    #pragma unroll
    for (int p = 0; p < 2; p++) {
        float lo[7], hi[7];
        #pragma unroll
        for (int j = 0; j < 7; j++) {
            unsigned int ulo, uhi;
            asm("mov.b64 {%0, %1}, %2;" : "=r"(ulo), "=r"(uhi) : "l"(accP[p][j]));
            lo[j] = __uint_as_float(ulo);
            hi[j] = __uint_as_float(uhi);
        }
        #pragma unroll
        for (int half = 0; half < 2; half++) {
            float* v = half ? hi : lo;
            int rowGlobal = blockRow + rbase + 2 * p + half;
            float m = v[0];
            #pragma unroll
            for (int j = 1; j < 7; j++) m = fmaxf(m, v[j]);
            float e[7], s = 0.0f;
            #pragma unroll
            for (int j = 0; j < 7; j++) { e[j] = __expf(v[j] - m); s += e[j]; }
            float inv = 1.0f / s;
            size_t n8 = ((size_t)rowGlobal * 8 + head) * 8;
            *(float4*)&g_weights[n8]     = make_float4(e[0]*inv, e[1]*inv, e[2]*inv, e[3]*inv);
            *(float4*)&g_weights[n8 + 4] = make_float4(e[4]*inv, e[5]*inv, e[6]*inv, 0.0f);
        }
    }
}

// ---------------------------------------------------------------------------
// Kernel 2: gathered conv. Block = (t-tile of 16, one b). 512 threads, thread
// owns one channel c for all 16 t. x staged in smem [22 x 512] (halo 3+3),
// weights staged [16 x 64]. Taps are 7 consecutive smem floats (lane stride 7
// words -> conflict-free since gcd(7,32)=1). smem = 48 KB -> 3 blocks/SM.
// ---------------------------------------------------------------------------
#define TT 16
#define XS_ROWS (TT + K_DIM - 1)            // 22
#define SMEM_CONV ((XS_ROWS * C_DIM + TT * 64) * 4)   // 49152 bytes

__global__ __launch_bounds__(512, 3)
void conv_kernel(const float* __restrict__ x, float* __restrict__ out) {
    extern __shared__ float smem[];
    float* xs = smem;                        // 22*512
    float* ws = smem + XS_ROWS * C_DIM;      // 16*64

    const int tid = threadIdx.x;
    const int t0  = (blockIdx.x >> 4) * TT;
    const int b   = blockIdx.x & 15;

    // ---- stage weights: per t, 64 contiguous floats (8 heads x 8 slots) ----
    if (tid < TT * 16) {
        int tl = tid >> 4;                   // 0..15
        int f4 = tid & 15;                   // 0..15
        const float4* src = (const float4*)(g_weights + (size_t)(t0 + tl) * (B_DIM * 64) + b * 64);
        *(float4*)&ws[tl * 64 + f4 * 4] = src[f4];
    }
    // ---- stage x tile with halo, zero-padded at sequence edges ----
    for (int linear = tid; linear < XS_ROWS * (C_DIM / 4); linear += 512) {
        int irow = linear >> 7;              // 0..21
        int c4   = linear & 127;
        int tg   = t0 - 3 + irow;
        float4 v = make_float4(0.0f, 0.0f, 0.0f, 0.0f);
        if (tg >= 0 && tg < T_DIM)
            v = *(const float4*)(x + ((size_t)tg * B_DIM + b) * C_DIM + c4 * 4);
        *(float4*)&xs[irow * C_DIM + c4 * 4] = v;
    }
    __syncthreads();

    const int c  = tid;
    const int h  = c >> 6;                   // uniform per warp
    const int fb = h * 448 + (c & 63) * 7;   // flat offset of first tap

    #pragma unroll 4
    for (int tl = 0; tl < TT; tl++) {
        const float4* wp = (const float4*)&ws[tl * 64 + h * 8];   // broadcast
        float4 w0 = wp[0];
        float4 w1 = wp[1];
        const float* xp = &xs[tl * C_DIM + fb];   // 7 consecutive floats
        float acc;
        acc = w0.x * xp[0];
        acc = fmaf(w0.y, xp[1], acc);
        acc = fmaf(w0.z, xp[2], acc);
        acc = fmaf(w0.w, xp[3], acc);
        acc = fmaf(w1.x, xp[4], acc);
        acc = fmaf(w1.y, xp[5], acc);
        acc = fmaf(w1.z, xp[6], acc);
        out[((size_t)(t0 + tl) * B_DIM + b) * C_DIM + c] = acc;
    }
}

// ---------------------------------------------------------------------------
extern "C" void kernel_launch(void* const* d_in, const int* in_sizes, int n_in,
                              void* d_out, int out_size) {
    const float* x     = (const float*)d_in[0];
    const float* query = (const float*)d_in[1];
    const float* W     = (const float*)d_in[2];
    float* out         = (float*)d_out;

    cudaFuncSetAttribute(conv_kernel, cudaFuncAttributeMaxDynamicSharedMemorySize, SMEM_CONV);

    // phase 1: 32768 rows / 128 = 256 blocks
    gemm_softmax_kernel<<<256, 256>>>(query, W);
    // phase 2: 128 t-tiles x 16 batches
    conv_kernel<<<(T_DIM / TT) * B_DIM, 512, SMEM_CONV>>>(x, out);
}